// round 14
// baseline (speedup 1.0000x reference)
#include <cuda_runtime.h>
#include <cuda_fp16.h>
#include <cstdint>

#define N_NODES 100000
#define N_EDGES 1600000
#define N_GRAPHS 2000
#define HID 128
#define BN_EPS 1e-5f

// ---------------- scratch (device globals; no allocation allowed) ----------------
__device__ __half g_yh[N_NODES * HID];    // y = (h @ W) * norm, fp16 (25.6 MB)
__device__ __half g_hh[N_NODES * HID];    // activations fp16        (25.6 MB)
__device__ float g_norm[N_NODES];
__device__ int   g_deg[N_NODES];
__device__ int   g_rowptr[N_NODES + 1];
__device__ int   g_cursor[N_NODES];
__device__ int   g_srcs[N_EDGES];         // CSR by dst (6.4 MB)
__device__ float g_pool[N_GRAPHS * HID];
__device__ float g_cnt[N_GRAPHS];
__device__ uint2 g_wpk[4 * 64 * HID];     // prepacked W fragments (hi,lo) per layer

#define SCAN_BLK 1024
#define SCAN_NB ((N_NODES + SCAN_BLK - 1) / SCAN_BLK)   // 98
__device__ int g_bsum[SCAN_NB];

// ---------------- setup kernels ----------------
__global__ void init_kernel() {
    int i = blockIdx.x * blockDim.x + threadIdx.x;
    int stride = gridDim.x * blockDim.x;
    for (int t = i; t < N_GRAPHS * HID; t += stride) g_pool[t] = 0.f;
    for (int t = i; t < N_NODES; t += stride) g_deg[t] = 0;
    for (int t = i; t < N_GRAPHS; t += stride) g_cnt[t] = 0.f;
}

// Split all 4 layer weights into fp16 (hi, lo) fragment pairs, once.
// Layout per layer: [64 kpairs][128 cols] of uint2( hi half2(k,k+1), lo half2(k,k+1) ).
__global__ __launch_bounds__(256) void prep_w_kernel(const float* __restrict__ Ws) {
    int t = blockIdx.x * blockDim.x + threadIdx.x;
    if (t >= 4 * 64 * HID) return;
    int l = t >> 13;
    int r = t & 8191;
    int kp = r >> 7;
    int c = r & 127;
    const float* W = Ws + (size_t)l * HID * HID;
    float fa = W[(size_t)(2 * kp) * HID + c];
    float fb = W[(size_t)(2 * kp + 1) * HID + c];
    __half ha = __float2half_rn(fa);
    __half hb = __float2half_rn(fb);
    __half la = __float2half_rn(fa - __half2float(ha));
    __half lb = __float2half_rn(fb - __half2float(hb));
    uint2 o;
    *reinterpret_cast<__half2*>(&o.x) = __halves2half2(ha, hb);
    *reinterpret_cast<__half2*>(&o.y) = __halves2half2(la, lb);
    g_wpk[t] = o;
}

__global__ void count_kernel(const int* __restrict__ dst) {
    int e = blockIdx.x * blockDim.x + threadIdx.x;
    if (e < N_EDGES) atomicAdd(&g_deg[dst[e]], 1);
}

// ---- 3-phase prefix scan over g_deg -> rowptr/cursor + norm ----
__global__ __launch_bounds__(256) void scan_reduce_kernel() {
    int b = blockIdx.x;
    int base = b * SCAN_BLK;
    int tid = threadIdx.x;
    int sum = 0;
    for (int i = tid; i < SCAN_BLK; i += 256) {
        int idx = base + i;
        if (idx < N_NODES) sum += g_deg[idx];
    }
    #pragma unroll
    for (int o = 16; o > 0; o >>= 1) sum += __shfl_down_sync(0xFFFFFFFFu, sum, o);
    __shared__ int ws[8];
    int lane = tid & 31, wid = tid >> 5;
    if (lane == 0) ws[wid] = sum;
    __syncthreads();
    if (tid == 0) {
        int t = 0;
        #pragma unroll
        for (int i = 0; i < 8; i++) t += ws[i];
        g_bsum[b] = t;
    }
}

// scan 98 partials with one 128-thread block
__global__ __launch_bounds__(128) void scan_partials_kernel() {
    int tid = threadIdx.x;
    int lane = tid & 31, wid = tid >> 5;
    int v = (tid < SCAN_NB) ? g_bsum[tid] : 0;
    int x = v;
    #pragma unroll
    for (int o = 1; o < 32; o <<= 1) {
        int t = __shfl_up_sync(0xFFFFFFFFu, x, o);
        if (lane >= o) x += t;
    }
    __shared__ int ws[4];
    if (lane == 31) ws[wid] = x;
    __syncthreads();
    int off = 0;
    #pragma unroll
    for (int w = 0; w < 4; w++) if (w < wid) off += ws[w];
    if (tid < SCAN_NB) g_bsum[tid] = off + x - v;   // exclusive
    if (tid == 127) g_rowptr[N_NODES] = off + x;
}

__global__ __launch_bounds__(256) void scan_final_kernel() {
    int b = blockIdx.x;
    int base = b * SCAN_BLK;
    int tid = threadIdx.x;
    int lane = tid & 31, wid = tid >> 5;
    int i0 = base + tid * 4;
    int v0 = 0, v1 = 0, v2 = 0, v3 = 0;
    if (i0 + 3 < N_NODES) {
        int4 v = *reinterpret_cast<const int4*>(&g_deg[i0]);
        v0 = v.x; v1 = v.y; v2 = v.z; v3 = v.w;
    } else {
        if (i0 < N_NODES) v0 = g_deg[i0];
        if (i0 + 1 < N_NODES) v1 = g_deg[i0 + 1];
        if (i0 + 2 < N_NODES) v2 = g_deg[i0 + 2];
        if (i0 + 3 < N_NODES) v3 = g_deg[i0 + 3];
    }
    int t0 = v0, t1 = t0 + v1, t2 = t1 + v2, t3 = t2 + v3;
    int ts = t3;
    int ws_i = ts;
    #pragma unroll
    for (int o = 1; o < 32; o <<= 1) {
        int t = __shfl_up_sync(0xFFFFFFFFu, ws_i, o);
        if (lane >= o) ws_i += t;
    }
    __shared__ int wsum[8];
    if (lane == 31) wsum[wid] = ws_i;
    __syncthreads();
    int woff = 0;
    #pragma unroll
    for (int w = 0; w < 8; w++) if (w < wid) woff += wsum[w];
    int excl = g_bsum[b] + (ws_i - ts) + woff;
    int e0 = excl, e1 = excl + t0, e2 = excl + t1, e3 = excl + t2;
    if (i0 < N_NODES)     { g_rowptr[i0] = e0;   g_cursor[i0] = e0;   g_norm[i0] = rsqrtf((float)v0 + 1.f); }
    if (i0 + 1 < N_NODES) { g_rowptr[i0+1] = e1; g_cursor[i0+1] = e1; g_norm[i0+1] = rsqrtf((float)v1 + 1.f); }
    if (i0 + 2 < N_NODES) { g_rowptr[i0+2] = e2; g_cursor[i0+2] = e2; g_norm[i0+2] = rsqrtf((float)v2 + 1.f); }
    if (i0 + 3 < N_NODES) { g_rowptr[i0+3] = e3; g_cursor[i0+3] = e3; g_norm[i0+3] = rsqrtf((float)v3 + 1.f); }
}

__global__ void scatter_kernel(const int* __restrict__ src, const int* __restrict__ dst) {
    int e = blockIdx.x * blockDim.x + threadIdx.x;
    if (e < N_EDGES) {
        int d = dst[e];
        int pos = atomicAdd(&g_cursor[d], 1);
        g_srcs[pos] = src[e];
    }
}

// ---------------- fp16 tensor-core GEMM: y = (h_fp16 @ W) * norm -> fp16 ----------------
// A fp16 exact (layer 0 converts fp32 x inline while staging, same rn rounding).
// W prepacked (hi,lo) in g_wpk: 2-pass HMMA m16n8k16, fp32 accumulate.
//   A2[row][kblk*4+j]  = uint2( half2@kpair(kblk*8+j), half2@kpair(kblk*8+j+4) )
//   B2[kpair][n]       = uint2( hi half2(k,k+1), lo half2(k,k+1) )
// Pitches 36/132 uint2 (both ==4 mod 16) -> all LDS.64 bank-pair bijective.
#define LDA2U 36
#define LDB2U 132
#define GEMM_F16_SMEM ((128 * LDA2U + 64 * LDB2U) * 8)

__device__ __forceinline__ void mma_f16(float4& d, uint32_t a0, uint32_t a1,
                                        uint32_t a2, uint32_t a3,
                                        uint32_t b0, uint32_t b1) {
    asm volatile(
        "mma.sync.aligned.m16n8k16.row.col.f32.f16.f16.f32 "
        "{%0,%1,%2,%3}, {%4,%5,%6,%7}, {%8,%9}, {%0,%1,%2,%3};"
        : "+f"(d.x), "+f"(d.y), "+f"(d.z), "+f"(d.w)
        : "r"(a0), "r"(a1), "r"(a2), "r"(a3), "r"(b0), "r"(b1));
}

__device__ __forceinline__ uint32_t h2pack(float a, float b) {
    __half2 h = __floats2half2_rn(a, b);
    return *reinterpret_cast<uint32_t*>(&h);
}

__global__ __launch_bounds__(256, 2) void gemm_f16_kernel(const float* __restrict__ x,
                                                          int layer, int first) {
    extern __shared__ uint2 smu[];
    uint2* A2 = smu;                    // [128][LDA2U]
    uint2* B2 = smu + 128 * LDA2U;      // [64][LDB2U]
    int tid = threadIdx.x;
    int m0 = blockIdx.x * 128;
    int lane = tid & 31, wid = tid >> 5;
    int warpM = wid >> 1, warpN = wid & 1;
    int mbase = warpM * 32, nbase = warpN * 64;
    int gr = lane >> 2, gc = lane & 3;

    // ---- stage A: 128 rows x 8 kblks, pack (j, j+4) kpair interleave ----
    if (first) {
        #pragma unroll
        for (int i = 0; i < 4; i++) {
            int t = tid + i * 256;
            int row = t >> 3, kblk = t & 7;
            float4 f0 = make_float4(0.f, 0.f, 0.f, 0.f), f1 = f0, f2 = f0, f3 = f0;
            if (m0 + row < N_NODES) {
                const float4* xr = reinterpret_cast<const float4*>(
                    x + (size_t)(m0 + row) * HID + kblk * 16);
                f0 = xr[0]; f1 = xr[1]; f2 = xr[2]; f3 = xr[3];
            }
            uint2* p = A2 + row * LDA2U + kblk * 4;
            p[0] = make_uint2(h2pack(f0.x, f0.y), h2pack(f2.x, f2.y));
            p[1] = make_uint2(h2pack(f0.z, f0.w), h2pack(f2.z, f2.w));
            p[2] = make_uint2(h2pack(f1.x, f1.y), h2pack(f3.x, f3.y));
            p[3] = make_uint2(h2pack(f1.z, f1.w), h2pack(f3.z, f3.w));
        }
    } else {
        #pragma unroll
        for (int i = 0; i < 4; i++) {
            int t = tid + i * 256;
            int row = t >> 3, kblk = t & 7;
            uint4 q0 = make_uint4(0, 0, 0, 0), q1 = make_uint4(0, 0, 0, 0);
            if (m0 + row < N_NODES) {
                const uint4* hr = reinterpret_cast<const uint4*>(g_hh + (size_t)(m0 + row) * HID);
                q0 = hr[kblk * 2];
                q1 = hr[kblk * 2 + 1];
            }
            uint2* p = A2 + row * LDA2U + kblk * 4;
            p[0] = make_uint2(q0.x, q1.x);
            p[1] = make_uint2(q0.y, q1.y);
            p[2] = make_uint2(q0.z, q1.z);
            p[3] = make_uint2(q0.w, q1.w);
        }
    }
    // ---- stage B: pure copy of prepacked fragments ----
    {
        const uint2* wpk = g_wpk + (size_t)layer * 64 * HID;
        #pragma unroll
        for (int i = 0; i < 8; i++) {
            int t = tid + i * 256;
            int kp = t >> 5;
            int c = (t & 31) << 2;
            const uint4* wsrc = reinterpret_cast<const uint4*>(wpk + kp * HID + c);
            uint4* p = reinterpret_cast<uint4*>(B2 + kp * LDB2U + c);
            p[0] = wsrc[0];
            p[1] = wsrc[1];
        }
    }
    __syncthreads();

    float4 acc[2][8];
    #pragma unroll
    for (int mf = 0; mf < 2; mf++)
        #pragma unroll
        for (int nf = 0; nf < 8; nf++)
            acc[mf][nf] = make_float4(0.f, 0.f, 0.f, 0.f);

    #pragma unroll
    for (int kblk = 0; kblk < 8; kblk++) {
        uint2 Aa[2], Ab[2];
        #pragma unroll
        for (int mf = 0; mf < 2; mf++) {
            int r = mbase + mf * 16 + gr;
            Aa[mf] = A2[r * LDA2U + kblk * 4 + gc];        // (a0, a2)
            Ab[mf] = A2[(r + 8) * LDA2U + kblk * 4 + gc];  // (a1, a3)
        }
        #pragma unroll
        for (int nf = 0; nf < 8; nf++) {
            int n = nbase + nf * 8 + gr;
            uint2 b0 = B2[(kblk * 8 + gc) * LDB2U + n];        // (b0hi, b0lo)
            uint2 b1 = B2[(kblk * 8 + gc + 4) * LDB2U + n];    // (b1hi, b1lo)
            #pragma unroll
            for (int mf = 0; mf < 2; mf++) {
                mma_f16(acc[mf][nf], Aa[mf].x, Ab[mf].x, Aa[mf].y, Ab[mf].y, b0.x, b1.x);
                mma_f16(acc[mf][nf], Aa[mf].x, Ab[mf].x, Aa[mf].y, Ab[mf].y, b0.y, b1.y);
            }
        }
    }

    // epilogue: y = acc * norm[row], stored fp16
    #pragma unroll
    for (int mf = 0; mf < 2; mf++) {
        int r0 = m0 + mbase + mf * 16 + gr;
        int r1 = r0 + 8;
        float n0 = (r0 < N_NODES) ? g_norm[r0] : 0.f;
        float n1 = (r1 < N_NODES) ? g_norm[r1] : 0.f;
        #pragma unroll
        for (int nf = 0; nf < 8; nf++) {
            int c = nbase + nf * 8 + gc * 2;
            if (r0 < N_NODES) {
                __half2 v = __floats2half2_rn(acc[mf][nf].x * n0, acc[mf][nf].y * n0);
                *reinterpret_cast<__half2*>(g_yh + (size_t)r0 * HID + c) = v;
            }
            if (r1 < N_NODES) {
                __half2 v = __floats2half2_rn(acc[mf][nf].z * n1, acc[mf][nf].w * n1);
                *reinterpret_cast<__half2*>(g_yh + (size_t)r1 * HID + c) = v;
            }
        }
    }
}

// ---------------- aggregation + BN(eval) + ReLU, HALF-warp per node ----------------
// 16 lanes x uint4 (8 halves) per node row; 2 independent chains per warp.
// last!=0: fuse global-mean-pool instead of writing h.
__global__ __launch_bounds__(256) void agg_kernel(const float* __restrict__ bs,
                                                  const float* __restrict__ gam,
                                                  const float* __restrict__ bet,
                                                  const float* __restrict__ mean,
                                                  const float* __restrict__ var,
                                                  const int* __restrict__ batch,
                                                  int last) {
    int hw = threadIdx.x >> 4;          // half-warp id in block (0..15)
    int l16 = threadIdx.x & 15;         // lane within half-warp
    int n = blockIdx.x * 16 + hw;
    if (n >= N_NODES) return;
    const uint4* __restrict__ y4 = reinterpret_cast<const uint4*>(g_yh);

    float a0, a1, a2, a3, a4, a5, a6, a7;
    {
        uint4 sr = y4[(size_t)n * 16 + l16];   // self term: norm*y[n]
        float2 p0 = __half22float2(*reinterpret_cast<const __half2*>(&sr.x));
        float2 p1 = __half22float2(*reinterpret_cast<const __half2*>(&sr.y));
        float2 p2 = __half22float2(*reinterpret_cast<const __half2*>(&sr.z));
        float2 p3 = __half22float2(*reinterpret_cast<const __half2*>(&sr.w));
        a0 = p0.x; a1 = p0.y; a2 = p1.x; a3 = p1.y;
        a4 = p2.x; a5 = p2.y; a6 = p3.x; a7 = p3.y;
    }

    int e = g_rowptr[n], e1 = g_rowptr[n + 1];
    for (; e + 4 <= e1; e += 4) {
        int sA = g_srcs[e], sB = g_srcs[e + 1], sC = g_srcs[e + 2], sD = g_srcs[e + 3];
        uint4 rA = y4[(size_t)sA * 16 + l16];
        uint4 rB = y4[(size_t)sB * 16 + l16];
        uint4 rC = y4[(size_t)sC * 16 + l16];
        uint4 rD = y4[(size_t)sD * 16 + l16];
        float2 t;
        t = __half22float2(*reinterpret_cast<const __half2*>(&rA.x)); a0 += t.x; a1 += t.y;
        t = __half22float2(*reinterpret_cast<const __half2*>(&rA.y)); a2 += t.x; a3 += t.y;
        t = __half22float2(*reinterpret_cast<const __half2*>(&rA.z)); a4 += t.x; a5 += t.y;
        t = __half22float2(*reinterpret_cast<const __half2*>(&rA.w)); a6 += t.x; a7 += t.y;
        t = __half22float2(*reinterpret_cast<const __half2*>(&rB.x)); a0 += t.x; a1 += t.y;
        t = __half22float2(*reinterpret_cast<const __half2*>(&rB.y)); a2 += t.x; a3 += t.y;
        t = __half22float2(*reinterpret_cast<const __half2*>(&rB.z)); a4 += t.x; a5 += t.y;
        t = __half22float2(*reinterpret_cast<const __half2*>(&rB.w)); a6 += t.x; a7 += t.y;
        t = __half22float2(*reinterpret_cast<const __half2*>(&rC.x)); a0 += t.x; a1 += t.y;
        t = __half22float2(*reinterpret_cast<const __half2*>(&rC.y)); a2 += t.x; a3 += t.y;
        t = __half22float2(*reinterpret_cast<const __half2*>(&rC.z)); a4 += t.x; a5 += t.y;
        t = __half22float2(*reinterpret_cast<const __half2*>(&rC.w)); a6 += t.x; a7 += t.y;
        t = __half22float2(*reinterpret_cast<const __half2*>(&rD.x)); a0 += t.x; a1 += t.y;
        t = __half22float2(*reinterpret_cast<const __half2*>(&rD.y)); a2 += t.x; a3 += t.y;
        t = __half22float2(*reinterpret_cast<const __half2*>(&rD.z)); a4 += t.x; a5 += t.y;
        t = __half22float2(*reinterpret_cast<const __half2*>(&rD.w)); a6 += t.x; a7 += t.y;
    }
    for (; e < e1; e++) {
        int s = g_srcs[e];
        uint4 r = y4[(size_t)s * 16 + l16];
        float2 t;
        t = __half22float2(*reinterpret_cast<const __half2*>(&r.x)); a0 += t.x; a1 += t.y;
        t = __half22float2(*reinterpret_cast<const __half2*>(&r.y)); a2 += t.x; a3 += t.y;
        t = __half22float2(*reinterpret_cast<const __half2*>(&r.z)); a4 += t.x; a5 += t.y;
        t = __half22float2(*reinterpret_cast<const __half2*>(&r.w)); a6 += t.x; a7 += t.y;
    }

    float nrm = g_norm[n];
    int j = l16 * 8;
    float4 bA = *reinterpret_cast<const float4*>(bs + j);
    float4 bB = *reinterpret_cast<const float4*>(bs + j + 4);
    float4 gA = *reinterpret_cast<const float4*>(gam + j);
    float4 gB = *reinterpret_cast<const float4*>(gam + j + 4);
    float4 eA = *reinterpret_cast<const float4*>(bet + j);
    float4 eB = *reinterpret_cast<const float4*>(bet + j + 4);
    float4 mA = *reinterpret_cast<const float4*>(mean + j);
    float4 mB = *reinterpret_cast<const float4*>(mean + j + 4);
    float4 vA = *reinterpret_cast<const float4*>(var + j);
    float4 vB = *reinterpret_cast<const float4*>(var + j + 4);
    float r0 = fmaxf((nrm * a0 + bA.x - mA.x) * (gA.x * rsqrtf(vA.x + BN_EPS)) + eA.x, 0.f);
    float r1 = fmaxf((nrm * a1 + bA.y - mA.y) * (gA.y * rsqrtf(vA.y + BN_EPS)) + eA.y, 0.f);
    float r2 = fmaxf((nrm * a2 + bA.z - mA.z) * (gA.z * rsqrtf(vA.z + BN_EPS)) + eA.z, 0.f);
    float r3 = fmaxf((nrm * a3 + bA.w - mA.w) * (gA.w * rsqrtf(vA.w + BN_EPS)) + eA.w, 0.f);
    float r4 = fmaxf((nrm * a4 + bB.x - mB.x) * (gB.x * rsqrtf(vB.x + BN_EPS)) + eB.x, 0.f);
    float r5 = fmaxf((nrm * a5 + bB.y - mB.y) * (gB.y * rsqrtf(vB.y + BN_EPS)) + eB.y, 0.f);
    float r6 = fmaxf((nrm * a6 + bB.z - mB.z) * (gB.z * rsqrtf(vB.z + BN_EPS)) + eB.z, 0.f);
    float r7 = fmaxf((nrm * a7 + bB.w - mB.w) * (gB.w * rsqrtf(vB.w + BN_EPS)) + eB.w, 0.f);

    if (!last) {
        uint4 packed;
        *reinterpret_cast<__half2*>(&packed.x) = __floats2half2_rn(r0, r1);
        *reinterpret_cast<__half2*>(&packed.y) = __floats2half2_rn(r2, r3);
        *reinterpret_cast<__half2*>(&packed.z) = __floats2half2_rn(r4, r5);
        *reinterpret_cast<__half2*>(&packed.w) = __floats2half2_rn(r6, r7);
        reinterpret_cast<uint4*>(g_hh)[(size_t)n * 16 + l16] = packed;
    } else {
        int b = batch[n];
        float* p = &g_pool[b * HID + j];
        atomicAdd(p, r0);     atomicAdd(p + 1, r1);
        atomicAdd(p + 2, r2); atomicAdd(p + 3, r3);
        atomicAdd(p + 4, r4); atomicAdd(p + 5, r5);
        atomicAdd(p + 6, r6); atomicAdd(p + 7, r7);
        if (l16 == 0) atomicAdd(&g_cnt[b], 1.0f);
    }
}

// ---------------- final projection: out[g] = pooled[g] @ W_out + b_out ----------------
__global__ __launch_bounds__(128) void out_kernel(const float* __restrict__ W_out,
                                                  const float* __restrict__ b_out,
                                                  float* __restrict__ out) {
    int g = blockIdx.x;
    int tid = threadIdx.x;
    int lane = tid & 31, wid = tid >> 5;
    float cnt = fmaxf(g_cnt[g], 1.0f);
    float p = g_pool[g * HID + tid] / cnt;
    float v[5];
    #pragma unroll
    for (int o = 0; o < 5; o++) v[o] = p * W_out[tid * 5 + o];
    #pragma unroll
    for (int o = 0; o < 5; o++)
        #pragma unroll
        for (int off = 16; off > 0; off >>= 1)
            v[o] += __shfl_down_sync(0xFFFFFFFFu, v[o], off);
    __shared__ float sred[4][5];
    if (lane == 0) {
        #pragma unroll
        for (int o = 0; o < 5; o++) sred[wid][o] = v[o];
    }
    __syncthreads();
    if (tid < 5) {
        float s = sred[0][tid] + sred[1][tid] + sred[2][tid] + sred[3][tid] + b_out[tid];
        out[g * 5 + tid] = s;
    }
}

// ---------------- launch ----------------
extern "C" void kernel_launch(void* const* d_in, const int* in_sizes, int n_in,
                              void* d_out, int out_size) {
    const float* x      = (const float*)d_in[0];
    const int*   edge   = (const int*)d_in[1];
    const int*   batch  = (const int*)d_in[2];
    const float* Ws     = (const float*)d_in[3];
    const float* bs     = (const float*)d_in[4];
    const float* gammas = (const float*)d_in[5];
    const float* betas  = (const float*)d_in[6];
    const float* rmean  = (const float*)d_in[7];
    const float* rvar   = (const float*)d_in[8];
    const float* W_out  = (const float*)d_in[9];
    const float* b_out  = (const float*)d_in[10];
    const int* src = edge;
    const int* dst = edge + N_EDGES;

    cudaFuncSetAttribute(gemm_f16_kernel,
                         cudaFuncAttributeMaxDynamicSharedMemorySize, GEMM_F16_SMEM);

    init_kernel<<<256, 256>>>();
    prep_w_kernel<<<(4 * 64 * HID + 255) / 256, 256>>>(Ws);
    count_kernel<<<(N_EDGES + 255) / 256, 256>>>(dst);
    scan_reduce_kernel<<<SCAN_NB, 256>>>();
    scan_partials_kernel<<<1, 128>>>();
    scan_final_kernel<<<SCAN_NB, 256>>>();
    scatter_kernel<<<(N_EDGES + 255) / 256, 256>>>(src, dst);

    int gemm_blocks = (N_NODES + 127) / 128;
    int agg_blocks = (N_NODES + 15) / 16;
    for (int l = 0; l < 4; l++) {
        gemm_f16_kernel<<<gemm_blocks, 256, GEMM_F16_SMEM>>>(x, l, l == 0 ? 1 : 0);
        agg_kernel<<<agg_blocks, 256>>>(bs + l * HID, gammas + l * HID,
                                        betas + l * HID, rmean + l * HID,
                                        rvar + l * HID, batch,
                                        l == 3 ? 1 : 0);
    }
    out_kernel<<<N_GRAPHS, 128>>>(W_out, b_out, (float*)d_out);
}

// round 16
// speedup vs baseline: 1.1217x; 1.1217x over previous
#include <cuda_runtime.h>
#include <cuda_fp16.h>
#include <cstdint>

#define N_NODES 100000
#define N_EDGES 1600000
#define N_GRAPHS 2000
#define HID 128
#define BN_EPS 1e-5f

// ---------------- scratch (device globals; no allocation allowed) ----------------
__device__ __half g_yh[N_NODES * HID];    // y = (h @ W) * norm, fp16 (25.6 MB)
__device__ __half g_hh[N_NODES * HID];    // activations fp16        (25.6 MB)
__device__ float g_norm[N_NODES];
__device__ int   g_deg[N_NODES];
__device__ int   g_rowptr[N_NODES + 1];
__device__ int   g_cursor[N_NODES];
__device__ int   g_srcs[N_EDGES];         // CSR by dst (6.4 MB)
__device__ float g_pool[N_GRAPHS * HID];
__device__ float g_cnt[N_GRAPHS];
// Prepacked W (hi plane only) in MMA fragment layout:
// per layer [32 rows = kblk*4+j][128 cols n] of uint2( half2@kpair(kblk*8+j), half2@kpair(kblk*8+j+4) )
__device__ uint2 g_wpk[4 * 32 * HID];

#define SCAN_BLK 1024
#define SCAN_NB ((N_NODES + SCAN_BLK - 1) / SCAN_BLK)   // 98
__device__ int g_bsum[SCAN_NB];

// ---------------- setup kernels ----------------
__global__ void init_kernel() {
    int i = blockIdx.x * blockDim.x + threadIdx.x;
    int stride = gridDim.x * blockDim.x;
    for (int t = i; t < N_GRAPHS * HID; t += stride) g_pool[t] = 0.f;
    for (int t = i; t < N_NODES; t += stride) g_deg[t] = 0;
    for (int t = i; t < N_GRAPHS; t += stride) g_cnt[t] = 0.f;
}

// Pack all 4 layer weights (fp16 hi) into fragment layout, once.
__global__ __launch_bounds__(256) void prep_w_kernel(const float* __restrict__ Ws) {
    int t = blockIdx.x * blockDim.x + threadIdx.x;
    if (t >= 4 * 32 * HID) return;
    int l = t >> 12;              // 4096 tasks per layer
    int r = t & 4095;
    int rowi = r >> 7;            // 0..31 = kblk*4 + j
    int n = r & 127;
    int kblk = rowi >> 2, j = rowi & 3;
    int kpA = kblk * 8 + j;
    int kpB = kpA + 4;
    const float* W = Ws + (size_t)l * HID * HID;
    __half2 hA = __floats2half2_rn(W[(size_t)(2 * kpA) * HID + n],
                                   W[(size_t)(2 * kpA + 1) * HID + n]);
    __half2 hB = __floats2half2_rn(W[(size_t)(2 * kpB) * HID + n],
                                   W[(size_t)(2 * kpB + 1) * HID + n]);
    uint2 o;
    o.x = *reinterpret_cast<uint32_t*>(&hA);
    o.y = *reinterpret_cast<uint32_t*>(&hB);
    g_wpk[t] = o;
}

__global__ void count_kernel(const int* __restrict__ dst) {
    int t = blockIdx.x * blockDim.x + threadIdx.x;
    if (t < N_EDGES / 4) {
        int4 d = reinterpret_cast<const int4*>(dst)[t];
        atomicAdd(&g_deg[d.x], 1);
        atomicAdd(&g_deg[d.y], 1);
        atomicAdd(&g_deg[d.z], 1);
        atomicAdd(&g_deg[d.w], 1);
    }
}

// ---- 3-phase prefix scan over g_deg -> rowptr/cursor + norm ----
__global__ __launch_bounds__(256) void scan_reduce_kernel() {
    int b = blockIdx.x;
    int base = b * SCAN_BLK;
    int tid = threadIdx.x;
    int sum = 0;
    for (int i = tid; i < SCAN_BLK; i += 256) {
        int idx = base + i;
        if (idx < N_NODES) sum += g_deg[idx];
    }
    #pragma unroll
    for (int o = 16; o > 0; o >>= 1) sum += __shfl_down_sync(0xFFFFFFFFu, sum, o);
    __shared__ int ws[8];
    int lane = tid & 31, wid = tid >> 5;
    if (lane == 0) ws[wid] = sum;
    __syncthreads();
    if (tid == 0) {
        int t = 0;
        #pragma unroll
        for (int i = 0; i < 8; i++) t += ws[i];
        g_bsum[b] = t;
    }
}

__global__ __launch_bounds__(128) void scan_partials_kernel() {
    int tid = threadIdx.x;
    int lane = tid & 31, wid = tid >> 5;
    int v = (tid < SCAN_NB) ? g_bsum[tid] : 0;
    int x = v;
    #pragma unroll
    for (int o = 1; o < 32; o <<= 1) {
        int t = __shfl_up_sync(0xFFFFFFFFu, x, o);
        if (lane >= o) x += t;
    }
    __shared__ int ws[4];
    if (lane == 31) ws[wid] = x;
    __syncthreads();
    int off = 0;
    #pragma unroll
    for (int w = 0; w < 4; w++) if (w < wid) off += ws[w];
    if (tid < SCAN_NB) g_bsum[tid] = off + x - v;   // exclusive
    if (tid == 127) g_rowptr[N_NODES] = off + x;
}

__global__ __launch_bounds__(256) void scan_final_kernel() {
    int b = blockIdx.x;
    int base = b * SCAN_BLK;
    int tid = threadIdx.x;
    int lane = tid & 31, wid = tid >> 5;
    int i0 = base + tid * 4;
    int v0 = 0, v1 = 0, v2 = 0, v3 = 0;
    if (i0 + 3 < N_NODES) {
        int4 v = *reinterpret_cast<const int4*>(&g_deg[i0]);
        v0 = v.x; v1 = v.y; v2 = v.z; v3 = v.w;
    } else {
        if (i0 < N_NODES) v0 = g_deg[i0];
        if (i0 + 1 < N_NODES) v1 = g_deg[i0 + 1];
        if (i0 + 2 < N_NODES) v2 = g_deg[i0 + 2];
        if (i0 + 3 < N_NODES) v3 = g_deg[i0 + 3];
    }
    int t0 = v0, t1 = t0 + v1, t2 = t1 + v2, t3 = t2 + v3;
    int ts = t3;
    int ws_i = ts;
    #pragma unroll
    for (int o = 1; o < 32; o <<= 1) {
        int t = __shfl_up_sync(0xFFFFFFFFu, ws_i, o);
        if (lane >= o) ws_i += t;
    }
    __shared__ int wsum[8];
    if (lane == 31) wsum[wid] = ws_i;
    __syncthreads();
    int woff = 0;
    #pragma unroll
    for (int w = 0; w < 8; w++) if (w < wid) woff += wsum[w];
    int excl = g_bsum[b] + (ws_i - ts) + woff;
    int e0 = excl, e1 = excl + t0, e2 = excl + t1, e3 = excl + t2;
    if (i0 < N_NODES)     { g_rowptr[i0] = e0;   g_cursor[i0] = e0;   g_norm[i0] = rsqrtf((float)v0 + 1.f); }
    if (i0 + 1 < N_NODES) { g_rowptr[i0+1] = e1; g_cursor[i0+1] = e1; g_norm[i0+1] = rsqrtf((float)v1 + 1.f); }
    if (i0 + 2 < N_NODES) { g_rowptr[i0+2] = e2; g_cursor[i0+2] = e2; g_norm[i0+2] = rsqrtf((float)v2 + 1.f); }
    if (i0 + 3 < N_NODES) { g_rowptr[i0+3] = e3; g_cursor[i0+3] = e3; g_norm[i0+3] = rsqrtf((float)v3 + 1.f); }
}

__global__ void scatter_kernel(const int* __restrict__ src, const int* __restrict__ dst) {
    int t = blockIdx.x * blockDim.x + threadIdx.x;
    if (t < N_EDGES / 4) {
        int4 s = reinterpret_cast<const int4*>(src)[t];
        int4 d = reinterpret_cast<const int4*>(dst)[t];
        int p0 = atomicAdd(&g_cursor[d.x], 1);
        int p1 = atomicAdd(&g_cursor[d.y], 1);
        int p2 = atomicAdd(&g_cursor[d.z], 1);
        int p3 = atomicAdd(&g_cursor[d.w], 1);
        g_srcs[p0] = s.x;
        g_srcs[p1] = s.y;
        g_srcs[p2] = s.z;
        g_srcs[p3] = s.w;
    }
}

// ---------------- fp16 tensor-core GEMM: y = (h_fp16 @ W_hi) * norm -> fp16 ----------------
// A fp16 exact (layer 0 converts fp32 x inline while staging). W single fp16 hi
// plane (prepacked fragments in g_wpk): 1-pass HMMA m16n8k16, fp32 accumulate.
//   A2[row][kblk*4+j]     = uint2( half2@kpair(kblk*8+j), half2@kpair(kblk*8+j+4) )
//   B2[kblk*4+j][n]       = uint2( b0 half2, b1 half2 )  (pitch 133)
// LDA2U=36 (==0 mod 4? 36%4=0... A mapping validated in R12), LDB2U=133
// (133 % 4 == 1 -> B frag addr = 4*gc + gr mod 16 bijective per LDS.64 phase).
#define LDA2U 36
#define LDB2U 133
#define GEMM_F16_SMEM ((128 * LDA2U + 32 * LDB2U) * 8)

__device__ __forceinline__ void mma_f16(float4& d, uint32_t a0, uint32_t a1,
                                        uint32_t a2, uint32_t a3,
                                        uint32_t b0, uint32_t b1) {
    asm volatile(
        "mma.sync.aligned.m16n8k16.row.col.f32.f16.f16.f32 "
        "{%0,%1,%2,%3}, {%4,%5,%6,%7}, {%8,%9}, {%0,%1,%2,%3};"
        : "+f"(d.x), "+f"(d.y), "+f"(d.z), "+f"(d.w)
        : "r"(a0), "r"(a1), "r"(a2), "r"(a3), "r"(b0), "r"(b1));
}

__device__ __forceinline__ uint32_t h2pack(float a, float b) {
    __half2 h = __floats2half2_rn(a, b);
    return *reinterpret_cast<uint32_t*>(&h);
}

__global__ __launch_bounds__(256, 2) void gemm_f16_kernel(const float* __restrict__ x,
                                                          int layer, int first) {
    extern __shared__ uint2 smu[];
    uint2* A2 = smu;                    // [128][LDA2U]
    uint2* B2 = smu + 128 * LDA2U;      // [32][LDB2U]
    int tid = threadIdx.x;
    int m0 = blockIdx.x * 128;
    int lane = tid & 31, wid = tid >> 5;
    int warpM = wid >> 1, warpN = wid & 1;
    int mbase = warpM * 32, nbase = warpN * 64;
    int gr = lane >> 2, gc = lane & 3;

    // ---- stage A: 128 rows x 8 kblks, pack (j, j+4) kpair interleave ----
    if (first) {
        #pragma unroll
        for (int i = 0; i < 4; i++) {
            int t = tid + i * 256;
            int row = t >> 3, kblk = t & 7;
            float4 f0 = make_float4(0.f, 0.f, 0.f, 0.f), f1 = f0, f2 = f0, f3 = f0;
            if (m0 + row < N_NODES) {
                const float4* xr = reinterpret_cast<const float4*>(
                    x + (size_t)(m0 + row) * HID + kblk * 16);
                f0 = xr[0]; f1 = xr[1]; f2 = xr[2]; f3 = xr[3];
            }
            uint2* p = A2 + row * LDA2U + kblk * 4;
            p[0] = make_uint2(h2pack(f0.x, f0.y), h2pack(f2.x, f2.y));
            p[1] = make_uint2(h2pack(f0.z, f0.w), h2pack(f2.z, f2.w));
            p[2] = make_uint2(h2pack(f1.x, f1.y), h2pack(f3.x, f3.y));
            p[3] = make_uint2(h2pack(f1.z, f1.w), h2pack(f3.z, f3.w));
        }
    } else {
        #pragma unroll
        for (int i = 0; i < 4; i++) {
            int t = tid + i * 256;
            int row = t >> 3, kblk = t & 7;
            uint4 q0 = make_uint4(0, 0, 0, 0), q1 = make_uint4(0, 0, 0, 0);
            if (m0 + row < N_NODES) {
                const uint4* hr = reinterpret_cast<const uint4*>(g_hh + (size_t)(m0 + row) * HID);
                q0 = hr[kblk * 2];
                q1 = hr[kblk * 2 + 1];
            }
            uint2* p = A2 + row * LDA2U + kblk * 4;
            p[0] = make_uint2(q0.x, q1.x);
            p[1] = make_uint2(q0.y, q1.y);
            p[2] = make_uint2(q0.z, q1.z);
            p[3] = make_uint2(q0.w, q1.w);
        }
    }
    // ---- stage B: copy prepacked fragments (32 x 128 uint2) ----
    {
        const uint2* wpk = g_wpk + (size_t)layer * 32 * HID;
        #pragma unroll
        for (int i = 0; i < 16; i++) {
            int t = tid + i * 256;
            int row = t >> 7, col = t & 127;
            B2[row * LDB2U + col] = wpk[t];
        }
    }
    __syncthreads();

    float4 acc[2][8];
    #pragma unroll
    for (int mf = 0; mf < 2; mf++)
        #pragma unroll
        for (int nf = 0; nf < 8; nf++)
            acc[mf][nf] = make_float4(0.f, 0.f, 0.f, 0.f);

    #pragma unroll
    for (int kblk = 0; kblk < 8; kblk++) {
        uint2 Aa[2], Ab[2];
        #pragma unroll
        for (int mf = 0; mf < 2; mf++) {
            int r = mbase + mf * 16 + gr;
            Aa[mf] = A2[r * LDA2U + kblk * 4 + gc];        // (a0, a2)
            Ab[mf] = A2[(r + 8) * LDA2U + kblk * 4 + gc];  // (a1, a3)
        }
        #pragma unroll
        for (int nf = 0; nf < 8; nf++) {
            int n = nbase + nf * 8 + gr;
            uint2 b = B2[(kblk * 4 + gc) * LDB2U + n];     // (b0, b1)
            #pragma unroll
            for (int mf = 0; mf < 2; mf++)
                mma_f16(acc[mf][nf], Aa[mf].x, Ab[mf].x, Aa[mf].y, Ab[mf].y, b.x, b.y);
        }
    }

    // epilogue: y = acc * norm[row], stored fp16
    #pragma unroll
    for (int mf = 0; mf < 2; mf++) {
        int r0 = m0 + mbase + mf * 16 + gr;
        int r1 = r0 + 8;
        float n0 = (r0 < N_NODES) ? g_norm[r0] : 0.f;
        float n1 = (r1 < N_NODES) ? g_norm[r1] : 0.f;
        #pragma unroll
        for (int nf = 0; nf < 8; nf++) {
            int c = nbase + nf * 8 + gc * 2;
            if (r0 < N_NODES) {
                __half2 v = __floats2half2_rn(acc[mf][nf].x * n0, acc[mf][nf].y * n0);
                *reinterpret_cast<__half2*>(g_yh + (size_t)r0 * HID + c) = v;
            }
            if (r1 < N_NODES) {
                __half2 v = __floats2half2_rn(acc[mf][nf].z * n1, acc[mf][nf].w * n1);
                *reinterpret_cast<__half2*>(g_yh + (size_t)r1 * HID + c) = v;
            }
        }
    }
}

// ---------------- aggregation + BN(eval) + ReLU, HALF-warp per node ----------------
__global__ __launch_bounds__(256) void agg_kernel(const float* __restrict__ bs,
                                                  const float* __restrict__ gam,
                                                  const float* __restrict__ bet,
                                                  const float* __restrict__ mean,
                                                  const float* __restrict__ var,
                                                  const int* __restrict__ batch,
                                                  int last) {
    int hw = threadIdx.x >> 4;
    int l16 = threadIdx.x & 15;
    int n = blockIdx.x * 16 + hw;
    if (n >= N_NODES) return;
    const uint4* __restrict__ y4 = reinterpret_cast<const uint4*>(g_yh);

    float a0, a1, a2, a3, a4, a5, a6, a7;
    {
        uint4 sr = y4[(size_t)n * 16 + l16];
        float2 p0 = __half22float2(*reinterpret_cast<const __half2*>(&sr.x));
        float2 p1 = __half22float2(*reinterpret_cast<const __half2*>(&sr.y));
        float2 p2 = __half22float2(*reinterpret_cast<const __half2*>(&sr.z));
        float2 p3 = __half22float2(*reinterpret_cast<const __half2*>(&sr.w));
        a0 = p0.x; a1 = p0.y; a2 = p1.x; a3 = p1.y;
        a4 = p2.x; a5 = p2.y; a6 = p3.x; a7 = p3.y;
    }

    int e = g_rowptr[n], e1 = g_rowptr[n + 1];
    for (; e + 4 <= e1; e += 4) {
        int sA = g_srcs[e], sB = g_srcs[e + 1], sC = g_srcs[e + 2], sD = g_srcs[e + 3];
        uint4 rA = y4[(size_t)sA * 16 + l16];
        uint4 rB = y4[(size_t)sB * 16 + l16];
        uint4 rC = y4[(size_t)sC * 16 + l16];
        uint4 rD = y4[(size_t)sD * 16 + l16];
        float2 t;
        t = __half22float2(*reinterpret_cast<const __half2*>(&rA.x)); a0 += t.x; a1 += t.y;
        t = __half22float2(*reinterpret_cast<const __half2*>(&rA.y)); a2 += t.x; a3 += t.y;
        t = __half22float2(*reinterpret_cast<const __half2*>(&rA.z)); a4 += t.x; a5 += t.y;
        t = __half22float2(*reinterpret_cast<const __half2*>(&rA.w)); a6 += t.x; a7 += t.y;
        t = __half22float2(*reinterpret_cast<const __half2*>(&rB.x)); a0 += t.x; a1 += t.y;
        t = __half22float2(*reinterpret_cast<const __half2*>(&rB.y)); a2 += t.x; a3 += t.y;
        t = __half22float2(*reinterpret_cast<const __half2*>(&rB.z)); a4 += t.x; a5 += t.y;
        t = __half22float2(*reinterpret_cast<const __half2*>(&rB.w)); a6 += t.x; a7 += t.y;
        t = __half22float2(*reinterpret_cast<const __half2*>(&rC.x)); a0 += t.x; a1 += t.y;
        t = __half22float2(*reinterpret_cast<const __half2*>(&rC.y)); a2 += t.x; a3 += t.y;
        t = __half22float2(*reinterpret_cast<const __half2*>(&rC.z)); a4 += t.x; a5 += t.y;
        t = __half22float2(*reinterpret_cast<const __half2*>(&rC.w)); a6 += t.x; a7 += t.y;
        t = __half22float2(*reinterpret_cast<const __half2*>(&rD.x)); a0 += t.x; a1 += t.y;
        t = __half22float2(*reinterpret_cast<const __half2*>(&rD.y)); a2 += t.x; a3 += t.y;
        t = __half22float2(*reinterpret_cast<const __half2*>(&rD.z)); a4 += t.x; a5 += t.y;
        t = __half22float2(*reinterpret_cast<const __half2*>(&rD.w)); a6 += t.x; a7 += t.y;
    }
    for (; e < e1; e++) {
        int s = g_srcs[e];
        uint4 r = y4[(size_t)s * 16 + l16];
        float2 t;
        t = __half22float2(*reinterpret_cast<const __half2*>(&r.x)); a0 += t.x; a1 += t.y;
        t = __half22float2(*reinterpret_cast<const __half2*>(&r.y)); a2 += t.x; a3 += t.y;
        t = __half22float2(*reinterpret_cast<const __half2*>(&r.z)); a4 += t.x; a5 += t.y;
        t = __half22float2(*reinterpret_cast<const __half2*>(&r.w)); a6 += t.x; a7 += t.y;
    }

    float nrm = g_norm[n];
    int j = l16 * 8;
    float4 bA = *reinterpret_cast<const float4*>(bs + j);
    float4 bB = *reinterpret_cast<const float4*>(bs + j + 4);
    float4 gA = *reinterpret_cast<const float4*>(gam + j);
    float4 gB = *reinterpret_cast<const float4*>(gam + j + 4);
    float4 eA = *reinterpret_cast<const float4*>(bet + j);
    float4 eB = *reinterpret_cast<const float4*>(bet + j + 4);
    float4 mA = *reinterpret_cast<const float4*>(mean + j);
    float4 mB = *reinterpret_cast<const float4*>(mean + j + 4);
    float4 vA = *reinterpret_cast<const float4*>(var + j);
    float4 vB = *reinterpret_cast<const float4*>(var + j + 4);
    float r0 = fmaxf((nrm * a0 + bA.x - mA.x) * (gA.x * rsqrtf(vA.x + BN_EPS)) + eA.x, 0.f);
    float r1 = fmaxf((nrm * a1 + bA.y - mA.y) * (gA.y * rsqrtf(vA.y + BN_EPS)) + eA.y, 0.f);
    float r2 = fmaxf((nrm * a2 + bA.z - mA.z) * (gA.z * rsqrtf(vA.z + BN_EPS)) + eA.z, 0.f);
    float r3 = fmaxf((nrm * a3 + bA.w - mA.w) * (gA.w * rsqrtf(vA.w + BN_EPS)) + eA.w, 0.f);
    float r4 = fmaxf((nrm * a4 + bB.x - mB.x) * (gB.x * rsqrtf(vB.x + BN_EPS)) + eB.x, 0.f);
    float r5 = fmaxf((nrm * a5 + bB.y - mB.y) * (gB.y * rsqrtf(vB.y + BN_EPS)) + eB.y, 0.f);
    float r6 = fmaxf((nrm * a6 + bB.z - mB.z) * (gB.z * rsqrtf(vB.z + BN_EPS)) + eB.z, 0.f);
    float r7 = fmaxf((nrm * a7 + bB.w - mB.w) * (gB.w * rsqrtf(vB.w + BN_EPS)) + eB.w, 0.f);

    if (!last) {
        uint4 packed;
        *reinterpret_cast<__half2*>(&packed.x) = __floats2half2_rn(r0, r1);
        *reinterpret_cast<__half2*>(&packed.y) = __floats2half2_rn(r2, r3);
        *reinterpret_cast<__half2*>(&packed.z) = __floats2half2_rn(r4, r5);
        *reinterpret_cast<__half2*>(&packed.w) = __floats2half2_rn(r6, r7);
        reinterpret_cast<uint4*>(g_hh)[(size_t)n * 16 + l16] = packed;
    } else {
        int b = batch[n];
        float* p = &g_pool[b * HID + j];
        atomicAdd(p, r0);     atomicAdd(p + 1, r1);
        atomicAdd(p + 2, r2); atomicAdd(p + 3, r3);
        atomicAdd(p + 4, r4); atomicAdd(p + 5, r5);
        atomicAdd(p + 6, r6); atomicAdd(p + 7, r7);
        if (l16 == 0) atomicAdd(&g_cnt[b], 1.0f);
    }
}

// ---------------- final projection: out[g] = pooled[g] @ W_out + b_out ----------------
__global__ __launch_bounds__(128) void out_kernel(const float* __restrict__ W_out,
                                                  const float* __restrict__ b_out,
                                                  float* __restrict__ out) {
    int g = blockIdx.x;
    int tid = threadIdx.x;
    int lane = tid & 31, wid = tid >> 5;
    float cnt = fmaxf(g_cnt[g], 1.0f);
    float p = g_pool[g * HID + tid] / cnt;
    float v[5];
    #pragma unroll
    for (int o = 0; o < 5; o++) v[o] = p * W_out[tid * 5 + o];
    #pragma unroll
    for (int o = 0; o < 5; o++)
        #pragma unroll
        for (int off = 16; off > 0; off >>= 1)
            v[o] += __shfl_down_sync(0xFFFFFFFFu, v[o], off);
    __shared__ float sred[4][5];
    if (lane == 0) {
        #pragma unroll
        for (int o = 0; o < 5; o++) sred[wid][o] = v[o];
    }
    __syncthreads();
    if (tid < 5) {
        float s = sred[0][tid] + sred[1][tid] + sred[2][tid] + sred[3][tid] + b_out[tid];
        out[g * 5 + tid] = s;
    }
}

// ---------------- launch ----------------
extern "C" void kernel_launch(void* const* d_in, const int* in_sizes, int n_in,
                              void* d_out, int out_size) {
    const float* x      = (const float*)d_in[0];
    const int*   edge   = (const int*)d_in[1];
    const int*   batch  = (const int*)d_in[2];
    const float* Ws     = (const float*)d_in[3];
    const float* bs     = (const float*)d_in[4];
    const float* gammas = (const float*)d_in[5];
    const float* betas  = (const float*)d_in[6];
    const float* rmean  = (const float*)d_in[7];
    const float* rvar   = (const float*)d_in[8];
    const float* W_out  = (const float*)d_in[9];
    const float* b_out  = (const float*)d_in[10];
    const int* src = edge;
    const int* dst = edge + N_EDGES;

    cudaFuncSetAttribute(gemm_f16_kernel,
                         cudaFuncAttributeMaxDynamicSharedMemorySize, GEMM_F16_SMEM);

    init_kernel<<<256, 256>>>();
    prep_w_kernel<<<(4 * 32 * HID + 255) / 256, 256>>>(Ws);
    count_kernel<<<(N_EDGES / 4 + 255) / 256, 256>>>(dst);
    scan_reduce_kernel<<<SCAN_NB, 256>>>();
    scan_partials_kernel<<<1, 128>>>();
    scan_final_kernel<<<SCAN_NB, 256>>>();
    scatter_kernel<<<(N_EDGES / 4 + 255) / 256, 256>>>(src, dst);

    int gemm_blocks = (N_NODES + 127) / 128;
    int agg_blocks = (N_NODES + 15) / 16;
    for (int l = 0; l < 4; l++) {
        gemm_f16_kernel<<<gemm_blocks, 256, GEMM_F16_SMEM>>>(x, l, l == 0 ? 1 : 0);
        agg_kernel<<<agg_blocks, 256>>>(bs + l * HID, gammas + l * HID,
                                        betas + l * HID, rmean + l * HID,
                                        rvar + l * HID, batch,
                                        l == 3 ? 1 : 0);
    }
    out_kernel<<<N_GRAPHS, 128>>>(W_out, b_out, (float*)d_out);
}